// round 6
// baseline (speedup 1.0000x reference)
#include <cuda_runtime.h>
#include <cuda_fp16.h>
#include <cstdint>

#define NTOK   65536
#define DIMC   256
#define NCODE  1024
#define HWSZ   4096
#define ZSZ    16777216
#define OFF_ZQ      1
#define OFF_PERP    16777217
#define OFF_MINENC  16777218ULL
#define OFF_IDX     83886082ULL

#define TOKT   128
#define MARGIN 1.2e-2f
#define CAP    24

// smem byte offsets (dynamic)
#define O_AH    0          // [128 k2][128 tok] half2 = 65536
#define O_BS    65536      // 2 x [128 k2][128 code] half2 = 131072
#define O_EN    196608     // 1024 f32 = 4096
#define O_SBEST 200704     // 128 u32
#define O_SCNT  201216     // 128 i32
#define O_SCAND 201728     // 128*24 i32 = 12288
#define SMEM_BYTES 214016

// ---------------- scratch ----------------
__device__ float   g_et[DIMC * NCODE];     // [c][k] for k_epi gather
__device__ __half2 g_eh2[128 * NCODE];     // [k2][code] half2 (dims 2k2,2k2+1)
__device__ float   g_en[NCODE];
__device__ int     g_idx[NTOK];
__device__ int     g_hist[NCODE];
__device__ double  g_loss;

__device__ __forceinline__ unsigned fenc(float f) {
    unsigned u = __float_as_uint(f);
    return (u & 0x80000000u) ? ~u : (u | 0x80000000u);
}
__device__ __forceinline__ float fdec(unsigned e) {
    unsigned u = (e & 0x80000000u) ? (e & 0x7FFFFFFFu) : ~e;
    return __uint_as_float(u);
}
#define ENC_FLT_MAX 0xFF7FFFFFu   /* fenc(3.402823e38f) */

#define CPA16(dst, src) \
    asm volatile("cp.async.cg.shared.global [%0], [%1], 16;" :: "r"(dst), "l"(src))
#define CPA_COMMIT() asm volatile("cp.async.commit_group;")
#define CPA_WAIT(n)  asm volatile("cp.async.wait_group %0;" :: "n"(n))

// ---------------- pass1: HFMA2 screen + exact fp32 re-rank ----------------
__global__ void __launch_bounds__(512, 1) k_pass1(const float* __restrict__ z,
                                                  const float* __restrict__ embed) {
    extern __shared__ char sm[];
    __half2*  AH    = (__half2*)(sm + O_AH);
    __half2*  BS    = (__half2*)(sm + O_BS);
    float*    EN    = (float*)(sm + O_EN);
    unsigned* sbest = (unsigned*)(sm + O_SBEST);
    int*      scnt  = (int*)(sm + O_SCNT);
    int*      scand = (int*)(sm + O_SCAND);

    const uint32_t bs_s = (uint32_t)__cvta_generic_to_shared(BS);

    int tid = threadIdx.x;
    int tx  = tid & 15;          // code group: 8 codes
    int ty  = tid >> 4;          // token group: 4 tokens (ty in [0,32))
    int n0  = blockIdx.x * TOKT;
    int b   = n0 >> 12, hw0 = n0 & 4095;
    const float* zb = z + (size_t)b * (DIMC * HWSZ) + hw0;

    // ---- issue cp.async for tile 0 ----
    {
        const char* src = (const char*)g_eh2;
#pragma unroll
        for (int j = 0; j < 8; j++) {
            int u = tid + j * 512;            // 4096 ops
            int k2 = u >> 5, c16 = u & 31;
            CPA16(bs_s + (uint32_t)(k2 * 512 + c16 * 16),
                  src + (size_t)k2 * 4096 + c16 * 16);
        }
        CPA_COMMIT();
    }

    // ---- init smem ----
    if (tid < 128) { sbest[tid] = ENC_FLT_MAX; scnt[tid] = 0; }
    for (int i = tid; i < NCODE; i += 512) EN[i] = g_en[i];

    // ---- convert AH[k2][tok] once (coalesced over tok) ----
#pragma unroll
    for (int j = 0; j < 32; j++) {
        int u = tid + j * 512;                // 16384 entries
        int tok = u & 127, k2 = u >> 7;
        float x = zb[(size_t)(2 * k2) * HWSZ + tok];
        float y = zb[(size_t)(2 * k2 + 1) * HWSZ + tok];
        AH[k2 * 128 + tok] = __floats2half2_rn(x, y);
    }

    float bv[4] = {3.4e38f, 3.4e38f, 3.4e38f, 3.4e38f};

    CPA_WAIT(0);
    __syncthreads();

    for (int T = 0; T < 8; T++) {
        int buf = T & 1;
        // prefetch tile T+1 into other buffer (prev compute on it is done)
        if (T < 7) {
            const char* src = (const char*)g_eh2 + (size_t)(T + 1) * 512;
            uint32_t dst = bs_s + (uint32_t)((1 - buf) * 65536);
#pragma unroll
            for (int j = 0; j < 8; j++) {
                int u = tid + j * 512;
                int k2 = u >> 5, c16 = u & 31;
                CPA16(dst + (uint32_t)(k2 * 512 + c16 * 16),
                      src + (size_t)k2 * 4096 + c16 * 16);
            }
            CPA_COMMIT();
            CPA_WAIT(1);
        } else {
            CPA_WAIT(0);
        }
        __syncthreads();

        // ---- compute: 2 halves of 64 k2-steps, fp16 acc + fp32 fold ----
        float accf[4][8];
#pragma unroll
        for (int i = 0; i < 4; i++)
#pragma unroll
            for (int j = 0; j < 8; j++) accf[i][j] = 0.0f;

        const __half2* ah = AH + ty * 4;
        const __half2* bp = BS + buf * 16384 + tx * 8;

#pragma unroll
        for (int half = 0; half < 2; half++) {
            __half2 acc2[4][8];
#pragma unroll
            for (int i = 0; i < 4; i++)
#pragma unroll
                for (int j = 0; j < 8; j++) acc2[i][j] = __half2half2(__ushort_as_half(0));
            const __half2* ahh = ah + half * 64 * 128;
            const __half2* bph = bp + half * 64 * 128;
#pragma unroll 8
            for (int k2 = 0; k2 < 64; k2++) {
                __half2 a2[4], b2[8];
                *(float4*)a2       = *(const float4*)(ahh + k2 * 128);
                *(float4*)b2       = *(const float4*)(bph + k2 * 128);
                *(float4*)(b2 + 4) = *(const float4*)(bph + k2 * 128 + 4);
#pragma unroll
                for (int i = 0; i < 4; i++)
#pragma unroll
                    for (int j = 0; j < 8; j++)
                        acc2[i][j] = __hfma2(a2[i], b2[j], acc2[i][j]);
            }
#pragma unroll
            for (int i = 0; i < 4; i++)
#pragma unroll
                for (int j = 0; j < 8; j++) {
                    float2 f = __half22float2(acc2[i][j]);
                    accf[i][j] += f.x + f.y;
                }
        }

        // ---- epilogue: dp = en - 2*dot, push candidates ----
#pragma unroll
        for (int j = 0; j < 8; j++) {
            int code = T * 128 + tx * 8 + j;
            float enj = EN[code];
#pragma unroll
            for (int i = 0; i < 4; i++) {
                float dp = enj - 2.0f * accf[i][j];
                if (dp < bv[i] + MARGIN) {
                    if (dp < bv[i]) bv[i] = dp;
                    int row = ty * 4 + i;
                    unsigned old = atomicMin(&sbest[row], fenc(dp));
                    if (dp < fdec(old) + MARGIN) {
                        int pos = atomicAdd(&scnt[row], 1);
                        if (pos < CAP) scand[row * CAP + pos] = code;
                    }
                }
            }
        }
        __syncthreads();
    }

    // ---- exact fp32 re-rank: one token per thread (rows 0..127) ----
    if (tid < TOKT) {
        int row = tid;
        int m = scnt[row];
        if (m >= 1 && m <= CAP) {
            const float* zp = zb + row;
            float zn = 0.0f;
            for (int c = 0; c < DIMC; c++)
                zn = fmaf(zp[(size_t)c * HWSZ], zp[(size_t)c * HWSZ], zn);
            float bestx = 3.4e38f;
            int   besti = 0x7FFFFFFF;
            for (int g0 = 0; g0 < m; g0 += 8) {
                int gc = m - g0; if (gc > 8) gc = 8;
                int codes8[8];
#pragma unroll
                for (int q = 0; q < 8; q++)
                    codes8[q] = scand[row * CAP + g0 + (q < gc ? q : 0)];
                float dot[8];
#pragma unroll
                for (int q = 0; q < 8; q++) dot[q] = 0.0f;
                for (int c = 0; c < DIMC; c++) {
                    float zc = zp[(size_t)c * HWSZ];
#pragma unroll
                    for (int q = 0; q < 8; q++)
                        dot[q] = fmaf(zc, __ldg(&embed[(size_t)codes8[q] * DIMC + c]), dot[q]);
                }
#pragma unroll
                for (int q = 0; q < 8; q++) {
                    if (q < gc) {
                        int code = codes8[q];
                        float v = (zn + EN[code]) - 2.0f * dot[q];
                        if (v < bestx || (v == bestx && code < besti)) {
                            bestx = v; besti = code;
                        }
                    }
                }
            }
            g_idx[n0 + row] = besti;
        }
    }
    __syncthreads();

    // ---- fallback: warp-cooperative exact full scan (overflow or empty) ----
    {
        int wz = tid >> 5, lane = tid & 31;
        for (int r = wz; r < TOKT; r += 16) {
            int m = scnt[r];
            if (m > CAP || m == 0) {
                const float* zp = zb + r;
                float zn = 0.0f;
                for (int c = 0; c < DIMC; c++)
                    zn = fmaf(zp[(size_t)c * HWSZ], zp[(size_t)c * HWSZ], zn);
                float bvv = 3.4e38f; int bii = 0x7FFFFFFF;
                for (int code = lane; code < NCODE; code += 32) {
                    float dot = 0.0f;
                    for (int c = 0; c < DIMC; c++)
                        dot = fmaf(zp[(size_t)c * HWSZ],
                                   __ldg(&embed[(size_t)code * DIMC + c]), dot);
                    float v = (zn + EN[code]) - 2.0f * dot;
                    if (v < bvv) { bvv = v; bii = code; }
                }
#pragma unroll
                for (int o = 16; o; o >>= 1) {
                    float ov = __shfl_xor_sync(0xffffffffu, bvv, o);
                    int   oi = __shfl_xor_sync(0xffffffffu, bii, o);
                    if (ov < bvv || (ov == bvv && oi < bii)) { bvv = ov; bii = oi; }
                }
                if (lane == 0) g_idx[n0 + r] = bii;
            }
        }
    }
}

// ---------------- embed prep: transpose + half2 + |e|^2 + zero accum ----------------
__global__ void k_prep(const float* __restrict__ e) {
    int k = blockIdx.x;
    int t = threadIdx.x;                       // 64 threads, 4 dims each
    float4 v = ((const float4*)(e + (size_t)k * DIMC))[t];
    int c = t * 4;
    g_et[(c + 0) * NCODE + k] = v.x;
    g_et[(c + 1) * NCODE + k] = v.y;
    g_et[(c + 2) * NCODE + k] = v.z;
    g_et[(c + 3) * NCODE + k] = v.w;
    g_eh2[(2 * t + 0) * NCODE + k] = __floats2half2_rn(v.x, v.y);
    g_eh2[(2 * t + 1) * NCODE + k] = __floats2half2_rn(v.z, v.w);
    float s = v.x * v.x + v.y * v.y + v.z * v.z + v.w * v.w;
#pragma unroll
    for (int o = 16; o; o >>= 1) s += __shfl_down_sync(0xffffffffu, s, o);
    __shared__ float sh[2];
    if ((t & 31) == 0) sh[t >> 5] = s;
    __syncthreads();
    if (t == 0) {
        g_en[k]   = sh[0] + sh[1];
        g_hist[k] = 0;
        if (k == 0) g_loss = 0.0;
    }
}

// ---------------- z_q gather (vectorized) + loss ----------------
__global__ void k_epi(const float* __restrict__ z, float* __restrict__ out) {
    int i4  = blockIdx.x * 256 + threadIdx.x;      // over ZSZ/4
    int hw4 = i4 & 1023;
    int c   = (i4 >> 10) & 255;
    int b   = i4 >> 18;
    int4 kk = *(const int4*)(g_idx + (b << 12) + (hw4 << 2));
    float4 zv = ((const float4*)z)[i4];
    const float* row = g_et + c * NCODE;
    float dx = __ldg(&row[kk.x]) - zv.x;
    float dy = __ldg(&row[kk.y]) - zv.y;
    float dz = __ldg(&row[kk.z]) - zv.z;
    float dw = __ldg(&row[kk.w]) - zv.w;
    size_t o = OFF_ZQ + (size_t)i4 * 4;
    out[o + 0] = zv.x + dx;
    out[o + 1] = zv.y + dy;
    out[o + 2] = zv.z + dz;
    out[o + 3] = zv.w + dw;
    float s = dx * dx + dy * dy + dz * dz + dw * dw;
#pragma unroll
    for (int of = 16; of; of >>= 1) s += __shfl_down_sync(0xffffffffu, s, of);
    __shared__ float red[8];
    int t = threadIdx.x;
    if ((t & 31) == 0) red[t >> 5] = s;
    __syncthreads();
    if (t < 8) {
        float w = red[t];
#pragma unroll
        for (int of = 4; of; of >>= 1) w += __shfl_down_sync(0x000000ffu, w, of);
        if (t == 0) atomicAdd(&g_loss, (double)w);
    }
}

// ---------------- one-hot scatter + idx + histogram ----------------
__global__ void k_scat(float* __restrict__ out) {
    int n = blockIdx.x * 256 + threadIdx.x;
    int k = g_idx[n];
    out[OFF_MINENC + (size_t)n * NCODE + k] = 1.0f;
    out[OFF_IDX + n] = (float)k;
    atomicAdd(&g_hist[k], 1);
}

// ---------------- finalize ----------------
__global__ void k_fin(float* __restrict__ out) {
    int t = threadIdx.x;
    float em = (float)g_hist[t] * (1.0f / 65536.0f);
    float v = em * logf(em + 1e-10f);
    __shared__ float sh[32];
#pragma unroll
    for (int o = 16; o; o >>= 1) v += __shfl_down_sync(0xffffffffu, v, o);
    if ((t & 31) == 0) sh[t >> 5] = v;
    __syncthreads();
    if (t < 32) {
        float w = sh[t];
#pragma unroll
        for (int o = 16; o; o >>= 1) w += __shfl_down_sync(0xffffffffu, w, o);
        if (t == 0) {
            out[OFF_PERP] = expf(-w);
            out[0] = (float)(g_loss * (1.25 / 16777216.0));
        }
    }
}

// ---------------- launch ----------------
extern "C" void kernel_launch(void* const* d_in, const int* in_sizes, int n_in,
                              void* d_out, int out_size) {
    const float* z = (const float*)d_in[0];
    const float* e = (const float*)d_in[1];
    float* out = (float*)d_out;
    (void)in_sizes; (void)n_in; (void)out_size;

    static int attr_set = 0;
    if (!attr_set) {
        cudaFuncSetAttribute(k_pass1, cudaFuncAttributeMaxDynamicSharedMemorySize, SMEM_BYTES);
        attr_set = 1;
    }

    k_prep  <<<NCODE, 64>>>(e);
    k_pass1 <<<NTOK / TOKT, 512, SMEM_BYTES>>>(z, e);
    cudaMemsetAsync(out + OFF_MINENC, 0, 268435456ULL);
    k_epi   <<<ZSZ / 1024, 256>>>(z, out);
    k_scat  <<<NTOK / 256, 256>>>(out);
    k_fin   <<<1, 1024>>>(out);
}

// round 7
// speedup vs baseline: 6.9444x; 6.9444x over previous
#include <cuda_runtime.h>
#include <cuda_fp16.h>
#include <cstdint>

#define NTOK   65536
#define DIMC   256
#define NCODE  1024
#define HWSZ   4096
#define ZSZ    16777216
#define OFF_ZQ      1
#define OFF_PERP    16777217
#define OFF_MINENC  16777218ULL
#define OFF_IDX     83886082ULL

#define TOKT   128
#define MARGIN 1e-2f
#define CAP    24

// smem byte offsets (dynamic)
#define O_AH    0          // [128 k2][128 tok] half2 = 65536
#define O_BS    65536      // 2 x [128 k2][128 code] half2 = 131072
#define O_EN    196608     // 1024 f32 = 4096
#define O_SBEST 200704     // 128 u32
#define O_SCNT  201216     // 128 i32
#define O_SCAND 201728     // 128*24 i32 = 12288
#define SMEM_BYTES 214016

// ---------------- scratch ----------------
__device__ float   g_et[DIMC * NCODE];     // [c][k] for k_epi gather
__device__ __half2 g_eh2[128 * NCODE];     // [k2][code] half2 (dims 2k2,2k2+1)
__device__ float   g_en[NCODE];
__device__ int     g_idx[NTOK];
__device__ int     g_hist[NCODE];
__device__ double  g_loss;

__device__ __forceinline__ unsigned fenc(float f) {
    unsigned u = __float_as_uint(f);
    return (u & 0x80000000u) ? ~u : (u | 0x80000000u);
}
__device__ __forceinline__ float fdec(unsigned e) {
    unsigned u = (e & 0x80000000u) ? (e & 0x7FFFFFFFu) : ~e;
    return __uint_as_float(u);
}
#define ENC_FLT_MAX 0xFF7FFFFFu   /* fenc(3.402823e38f) */

#define CPA16(dst, src) \
    asm volatile("cp.async.cg.shared.global [%0], [%1], 16;" :: "r"(dst), "l"(src))
#define CPA_COMMIT() asm volatile("cp.async.commit_group;")
#define CPA_WAIT(n)  asm volatile("cp.async.wait_group %0;" :: "n"(n))

// ---------------- pass1: HFMA2 screen + exact fp32 re-rank ----------------
__global__ void __launch_bounds__(512, 1) k_pass1(const float* __restrict__ z,
                                                  const float* __restrict__ embed) {
    extern __shared__ char sm[];
    __half2*  AH    = (__half2*)(sm + O_AH);
    __half2*  BS    = (__half2*)(sm + O_BS);
    float*    EN    = (float*)(sm + O_EN);
    unsigned* sbest = (unsigned*)(sm + O_SBEST);
    int*      scnt  = (int*)(sm + O_SCNT);
    int*      scand = (int*)(sm + O_SCAND);

    const uint32_t bs_s = (uint32_t)__cvta_generic_to_shared(BS);

    int tid = threadIdx.x;
    int tx  = tid & 15;          // code group: 8 codes
    int ty  = tid >> 4;          // token group: 4 tokens (ty in [0,32))
    int n0  = blockIdx.x * TOKT;
    int b   = n0 >> 12, hw0 = n0 & 4095;
    const float* zb = z + (size_t)b * (DIMC * HWSZ) + hw0;

    // ---- issue cp.async for tile 0 ----
    {
        const char* src = (const char*)g_eh2;
#pragma unroll
        for (int j = 0; j < 8; j++) {
            int u = tid + j * 512;            // 4096 ops
            int k2 = u >> 5, c16 = u & 31;
            CPA16(bs_s + (uint32_t)(k2 * 512 + c16 * 16),
                  src + (size_t)k2 * 4096 + c16 * 16);
        }
        CPA_COMMIT();
    }

    // ---- init smem ----
    if (tid < 128) { sbest[tid] = ENC_FLT_MAX; scnt[tid] = 0; }
    for (int i = tid; i < NCODE; i += 512) EN[i] = g_en[i];

    // ---- convert AH[k2][tok] once (coalesced over tok) ----
#pragma unroll
    for (int j = 0; j < 32; j++) {
        int u = tid + j * 512;                // 16384 entries
        int tok = u & 127, k2 = u >> 7;
        float x = zb[(size_t)(2 * k2) * HWSZ + tok];
        float y = zb[(size_t)(2 * k2 + 1) * HWSZ + tok];
        AH[k2 * 128 + tok] = __floats2half2_rn(x, y);
    }

    CPA_WAIT(0);
    __syncthreads();

    for (int T = 0; T < 8; T++) {
        int buf = T & 1;
        // prefetch tile T+1 into other buffer (prev compute on it is done)
        if (T < 7) {
            const char* src = (const char*)g_eh2 + (size_t)(T + 1) * 512;
            uint32_t dst = bs_s + (uint32_t)((1 - buf) * 65536);
#pragma unroll
            for (int j = 0; j < 8; j++) {
                int u = tid + j * 512;
                int k2 = u >> 5, c16 = u & 31;
                CPA16(dst + (uint32_t)(k2 * 512 + c16 * 16),
                      src + (size_t)k2 * 4096 + c16 * 16);
            }
            CPA_COMMIT();
            CPA_WAIT(1);
        } else {
            CPA_WAIT(0);
        }
        __syncthreads();

        // ---- compute: full K=256 (128 k2 steps), fp16 accumulation ----
        __half2 acc2[4][8];
#pragma unroll
        for (int i = 0; i < 4; i++)
#pragma unroll
            for (int j = 0; j < 8; j++) acc2[i][j] = __half2half2(__ushort_as_half(0));

        const __half2* ah = AH + ty * 4;
        const __half2* bp = BS + buf * 16384 + tx * 8;

#pragma unroll 8
        for (int k2 = 0; k2 < 128; k2++) {
            __half2 a2[4], b2[8];
            *(float4*)a2       = *(const float4*)(ah + k2 * 128);
            *(float4*)b2       = *(const float4*)(bp + k2 * 128);
            *(float4*)(b2 + 4) = *(const float4*)(bp + k2 * 128 + 4);
#pragma unroll
            for (int i = 0; i < 4; i++)
#pragma unroll
                for (int j = 0; j < 8; j++)
                    acc2[i][j] = __hfma2(a2[i], b2[j], acc2[i][j]);
        }

        // ---- phase A: settle per-row running min ----
#pragma unroll
        for (int i = 0; i < 4; i++) {
            float rm = 3.4e38f;
#pragma unroll
            for (int j = 0; j < 8; j++) {
                float2 f = __half22float2(acc2[i][j]);
                float dp = EN[T * 128 + tx * 8 + j] - 2.0f * (f.x + f.y);
                if (dp < rm) rm = dp;
            }
            atomicMin(&sbest[ty * 4 + i], fenc(rm));
        }
        __syncthreads();

        // ---- phase B: push candidates against settled threshold ----
#pragma unroll
        for (int i = 0; i < 4; i++) {
            int row = ty * 4 + i;
            float thr = fdec(sbest[row]) + MARGIN;
#pragma unroll
            for (int j = 0; j < 8; j++) {
                float2 f = __half22float2(acc2[i][j]);
                int code = T * 128 + tx * 8 + j;
                float dp = EN[code] - 2.0f * (f.x + f.y);
                if (dp < thr) {
                    int pos = atomicAdd(&scnt[row], 1);
                    if (pos < CAP) scand[row * CAP + pos] = code;
                }
            }
        }
        __syncthreads();
    }

    // ---- final prune threshold & exact fp32 re-rank: one token per thread ----
    if (tid < TOKT) {
        int row = tid;
        int m = scnt[row];
        if (m >= 1 && m <= CAP) {
            float thr = fdec(sbest[row]) + MARGIN;
            const float* zp = zb + row;
            float zn = 0.0f;
            for (int c = 0; c < DIMC; c++)
                zn = fmaf(zp[(size_t)c * HWSZ], zp[(size_t)c * HWSZ], zn);
            float bestx = 3.4e38f;
            int   besti = 0x7FFFFFFF;
            for (int g0 = 0; g0 < m; g0 += 8) {
                int gc = m - g0; if (gc > 8) gc = 8;
                int codes8[8];
#pragma unroll
                for (int q = 0; q < 8; q++)
                    codes8[q] = scand[row * CAP + g0 + (q < gc ? q : 0)];
                float dot[8];
#pragma unroll
                for (int q = 0; q < 8; q++) dot[q] = 0.0f;
                for (int c = 0; c < DIMC; c++) {
                    float zc = zp[(size_t)c * HWSZ];
#pragma unroll
                    for (int q = 0; q < 8; q++)
                        dot[q] = fmaf(zc, __ldg(&embed[(size_t)codes8[q] * DIMC + c]), dot[q]);
                }
#pragma unroll
                for (int q = 0; q < 8; q++) {
                    if (q < gc) {
                        int code = codes8[q];
                        float v = (zn + EN[code]) - 2.0f * dot[q];
                        if (v < bestx || (v == bestx && code < besti)) {
                            bestx = v; besti = code;
                        }
                    }
                }
            }
            (void)thr;
            g_idx[n0 + row] = besti;
        }
    }
    __syncthreads();

    // ---- fallback: warp-cooperative exact full scan (overflow/empty, rare) ----
    {
        int wz = tid >> 5, lane = tid & 31;
        for (int r = wz; r < TOKT; r += 16) {
            int m = scnt[r];
            if (m > CAP || m == 0) {
                const float* zp = zb + r;
                float zn = 0.0f;
                for (int c = 0; c < DIMC; c++)
                    zn = fmaf(zp[(size_t)c * HWSZ], zp[(size_t)c * HWSZ], zn);
                float bvv = 3.4e38f; int bii = 0x7FFFFFFF;
                for (int code = lane; code < NCODE; code += 32) {
                    float dot = 0.0f;
                    for (int c = 0; c < DIMC; c++)
                        dot = fmaf(zp[(size_t)c * HWSZ],
                                   __ldg(&embed[(size_t)code * DIMC + c]), dot);
                    float v = (zn + EN[code]) - 2.0f * dot;
                    if (v < bvv) { bvv = v; bii = code; }
                }
#pragma unroll
                for (int o = 16; o; o >>= 1) {
                    float ov = __shfl_xor_sync(0xffffffffu, bvv, o);
                    int   oi = __shfl_xor_sync(0xffffffffu, bii, o);
                    if (ov < bvv || (ov == bvv && oi < bii)) { bvv = ov; bii = oi; }
                }
                if (lane == 0) g_idx[n0 + r] = bii;
            }
        }
    }
}

// ---------------- embed prep: transpose + half2 + |e|^2 + zero accum ----------------
__global__ void k_prep(const float* __restrict__ e) {
    int k = blockIdx.x;
    int t = threadIdx.x;                       // 64 threads, 4 dims each
    float4 v = ((const float4*)(e + (size_t)k * DIMC))[t];
    int c = t * 4;
    g_et[(c + 0) * NCODE + k] = v.x;
    g_et[(c + 1) * NCODE + k] = v.y;
    g_et[(c + 2) * NCODE + k] = v.z;
    g_et[(c + 3) * NCODE + k] = v.w;
    g_eh2[(2 * t + 0) * NCODE + k] = __floats2half2_rn(v.x, v.y);
    g_eh2[(2 * t + 1) * NCODE + k] = __floats2half2_rn(v.z, v.w);
    float s = v.x * v.x + v.y * v.y + v.z * v.z + v.w * v.w;
#pragma unroll
    for (int o = 16; o; o >>= 1) s += __shfl_down_sync(0xffffffffu, s, o);
    __shared__ float sh[2];
    if ((t & 31) == 0) sh[t >> 5] = s;
    __syncthreads();
    if (t == 0) {
        g_en[k]   = sh[0] + sh[1];
        g_hist[k] = 0;
        if (k == 0) g_loss = 0.0;
    }
}

// ---------------- z_q gather (vectorized) + loss ----------------
__global__ void k_epi(const float* __restrict__ z, float* __restrict__ out) {
    int i4  = blockIdx.x * 256 + threadIdx.x;      // over ZSZ/4
    int hw4 = i4 & 1023;
    int c   = (i4 >> 10) & 255;
    int b   = i4 >> 18;
    int4 kk = *(const int4*)(g_idx + (b << 12) + (hw4 << 2));
    float4 zv = ((const float4*)z)[i4];
    const float* row = g_et + c * NCODE;
    float dx = __ldg(&row[kk.x]) - zv.x;
    float dy = __ldg(&row[kk.y]) - zv.y;
    float dz = __ldg(&row[kk.z]) - zv.z;
    float dw = __ldg(&row[kk.w]) - zv.w;
    size_t o = OFF_ZQ + (size_t)i4 * 4;
    out[o + 0] = zv.x + dx;
    out[o + 1] = zv.y + dy;
    out[o + 2] = zv.z + dz;
    out[o + 3] = zv.w + dw;
    float s = dx * dx + dy * dy + dz * dz + dw * dw;
#pragma unroll
    for (int of = 16; of; of >>= 1) s += __shfl_down_sync(0xffffffffu, s, of);
    __shared__ float red[8];
    int t = threadIdx.x;
    if ((t & 31) == 0) red[t >> 5] = s;
    __syncthreads();
    if (t < 8) {
        float w = red[t];
#pragma unroll
        for (int of = 4; of; of >>= 1) w += __shfl_down_sync(0x000000ffu, w, of);
        if (t == 0) atomicAdd(&g_loss, (double)w);
    }
}

// ---------------- one-hot scatter + idx + histogram ----------------
__global__ void k_scat(float* __restrict__ out) {
    int n = blockIdx.x * 256 + threadIdx.x;
    int k = g_idx[n];
    out[OFF_MINENC + (size_t)n * NCODE + k] = 1.0f;
    out[OFF_IDX + n] = (float)k;
    atomicAdd(&g_hist[k], 1);
}

// ---------------- finalize ----------------
__global__ void k_fin(float* __restrict__ out) {
    int t = threadIdx.x;
    float em = (float)g_hist[t] * (1.0f / 65536.0f);
    float v = em * logf(em + 1e-10f);
    __shared__ float sh[32];
#pragma unroll
    for (int o = 16; o; o >>= 1) v += __shfl_down_sync(0xffffffffu, v, o);
    if ((t & 31) == 0) sh[t >> 5] = v;
    __syncthreads();
    if (t < 32) {
        float w = sh[t];
#pragma unroll
        for (int o = 16; o; o >>= 1) w += __shfl_down_sync(0xffffffffu, w, o);
        if (t == 0) {
            out[OFF_PERP] = expf(-w);
            out[0] = (float)(g_loss * (1.25 / 16777216.0));
        }
    }
}

// ---------------- launch ----------------
extern "C" void kernel_launch(void* const* d_in, const int* in_sizes, int n_in,
                              void* d_out, int out_size) {
    const float* z = (const float*)d_in[0];
    const float* e = (const float*)d_in[1];
    float* out = (float*)d_out;
    (void)in_sizes; (void)n_in; (void)out_size;

    static int attr_set = 0;
    if (!attr_set) {
        cudaFuncSetAttribute(k_pass1, cudaFuncAttributeMaxDynamicSharedMemorySize, SMEM_BYTES);
        attr_set = 1;
    }

    k_prep  <<<NCODE, 64>>>(e);
    k_pass1 <<<NTOK / TOKT, 512, SMEM_BYTES>>>(z, e);
    cudaMemsetAsync(out + OFF_MINENC, 0, 268435456ULL);
    k_epi   <<<ZSZ / 1024, 256>>>(z, out);
    k_scat  <<<NTOK / 256, 256>>>(out);
    k_fin   <<<1, 1024>>>(out);
}